// round 13
// baseline (speedup 1.0000x reference)
#include <cuda_runtime.h>
#include <cuda_bf16.h>
#include <math.h>
#include <float.h>
#include <stdint.h>

#define T_SEQ 2048
#define NH 16
#define HD 128
#define DIM 2048
#define QKV_DIM 6144

// ---- mma.sync bf16 primitives (base ISA, works at compute_103) ----
__device__ __forceinline__ uint32_t smem_u32(const void* p) {
    uint32_t a;
    asm("{ .reg .u64 t; cvta.to.shared.u64 t, %1; cvt.u32.u64 %0, t; }"
        : "=r"(a) : "l"(p));
    return a;
}
__device__ __forceinline__ void ldsm4(uint32_t* r, uint32_t addr) {
    asm volatile("ldmatrix.sync.aligned.m8n8.x4.shared.b16 {%0,%1,%2,%3}, [%4];"
                 : "=r"(r[0]), "=r"(r[1]), "=r"(r[2]), "=r"(r[3]) : "r"(addr));
}
__device__ __forceinline__ void ldsm4t(uint32_t* r, uint32_t addr) {
    asm volatile("ldmatrix.sync.aligned.m8n8.x4.trans.shared.b16 {%0,%1,%2,%3}, [%4];"
                 : "=r"(r[0]), "=r"(r[1]), "=r"(r[2]), "=r"(r[3]) : "r"(addr));
}
__device__ __forceinline__ void mma_bf16(float* c, const uint32_t* a, const uint32_t* b) {
    asm volatile(
        "mma.sync.aligned.m16n8k16.row.col.f32.bf16.bf16.f32 "
        "{%0,%1,%2,%3}, {%4,%5,%6,%7}, {%8,%9}, {%0,%1,%2,%3};"
        : "+f"(c[0]), "+f"(c[1]), "+f"(c[2]), "+f"(c[3])
        : "r"(a[0]), "r"(a[1]), "r"(a[2]), "r"(a[3]), "r"(b[0]), "r"(b[1]));
}
__device__ __forceinline__ uint32_t prmt_hi(float x, float y) {
    uint32_t r;
    asm("prmt.b32 %0, %1, %2, 0x7632;" : "=r"(r)
        : "r"(__float_as_uint(x)), "r"(__float_as_uint(y)));
    return r;
}
__device__ __forceinline__ float trunc_bf(float v) {
    return __uint_as_float(__float_as_uint(v) & 0xffff0000u);
}
__device__ __forceinline__ uint32_t cvt_bf2(float lo, float hi) {
    uint32_t r;
    asm("cvt.rn.bf16x2.f32 %0, %1, %2;" : "=r"(r) : "f"(hi), "f"(lo));
    return r;
}
__device__ __forceinline__ void cp_async16(uint32_t saddr, const void* gptr) {
    asm volatile("cp.async.cg.shared.global [%0], [%1], 16;" :: "r"(saddr), "l"(gptr));
}
#define CP_COMMIT() asm volatile("cp.async.commit_group;" ::: "memory")
#define CP_WAIT(n)  asm volatile("cp.async.wait_group %0;" :: "n"(n) : "memory")

// ---------------- global scratch (allocation-free rule) ----------------
__device__ float g_qkv[2L * T_SEQ * QKV_DIM];
__device__ __nv_bfloat16 g_xh[4096L * DIM],   g_xl[4096L * DIM];
__device__ __nv_bfloat16 g_wqh[(long)QKV_DIM * DIM], g_wql[(long)QKV_DIM * DIM];
__device__ __nv_bfloat16 g_woh[(long)DIM * DIM],     g_wol[(long)DIM * DIM];
__device__ __nv_bfloat16 g_ath[4096L * DIM],  g_atl[4096L * DIM];
__device__ __nv_bfloat16 g_qh[2L * NH * T_SEQ * HD], g_ql[2L * NH * T_SEQ * HD];
__device__ __nv_bfloat16 g_kh[2L * NH * T_SEQ * HD], g_kl[2L * NH * T_SEQ * HD];
__device__ __nv_bfloat16 g_vh[2L * NH * T_SEQ * HD], g_vl[2L * NH * T_SEQ * HD];

// ---------------------------------------------------------------------------
// fused fp32 -> bf16 hi/lo split for x, w_qkv, w_out (one launch)
// ---------------------------------------------------------------------------
#define N4_X  (4096 * DIM / 4)
#define N4_WQ (QKV_DIM * DIM / 4)
#define N4_WO (DIM * DIM / 4)

__global__ __launch_bounds__(256) void split_all(const float* __restrict__ x,
                                                 const float* __restrict__ wq,
                                                 const float* __restrict__ wo) {
    int i = blockIdx.x * 256 + threadIdx.x;
    const float* src;
    __nv_bfloat16 *dh, *dl;
    int j;
    if (i < N4_X) {
        src = x; dh = g_xh; dl = g_xl; j = i;
    } else if (i < N4_X + N4_WQ) {
        src = wq; dh = g_wqh; dl = g_wql; j = i - N4_X;
    } else if (i < N4_X + N4_WQ + N4_WO) {
        src = wo; dh = g_woh; dl = g_wol; j = i - N4_X - N4_WQ;
    } else return;
    float4 v = ((const float4*)src)[j];
    uint32_t h01 = prmt_hi(v.x, v.y), h23 = prmt_hi(v.z, v.w);
    uint32_t l01 = cvt_bf2(v.x - trunc_bf(v.x), v.y - trunc_bf(v.y));
    uint32_t l23 = cvt_bf2(v.z - trunc_bf(v.z), v.w - trunc_bf(v.w));
    ((uint2*)dh)[j] = make_uint2(h01, h23);
    ((uint2*)dl)[j] = make_uint2(l01, l23);
}

// ---------------------------------------------------------------------------
// Pre-split bf16x3 GEMM, 64x64 warp tiles (R11 best: 4-stage depth-3)
// ---------------------------------------------------------------------------
#define NSTG 4
#define STG_SZ 24576
#define GEMM_SMEM (NSTG * STG_SZ)   // 98304 B

__global__ __launch_bounds__(128, 2) void gemm_presplit(
    const __nv_bfloat16* __restrict__ Ah, const __nv_bfloat16* __restrict__ Al,
    const __nv_bfloat16* __restrict__ Bh, const __nv_bfloat16* __restrict__ Bl,
    float* __restrict__ C, int N, int K) {
    extern __shared__ char sm[];
    uint32_t sb = smem_u32(sm);
    int tid = threadIdx.x, lane = tid & 31, wid = tid >> 5;
    int wm = wid >> 1, wn = wid & 1;

    size_t arow = (size_t)blockIdx.y * 128;
    size_t brow = (size_t)blockIdx.x * 128;

    int cprow = tid >> 1;
    int half = tid & 1;
    uint32_t cpso0 = (uint32_t)(cprow * 48 + half * 16);
    uint32_t cpso1 = (uint32_t)((cprow + 64) * 48 + half * 16);
    const __nv_bfloat16* pAh = Ah + (arow + cprow) * K + half * 8;
    const __nv_bfloat16* pAl = Al + (arow + cprow) * K + half * 8;
    const __nv_bfloat16* pBh = Bh + (brow + cprow) * K + half * 8;
    const __nv_bfloat16* pBl = Bl + (brow + cprow) * K + half * 8;
    size_t r64 = (size_t)64 * K;

    uint32_t a_off = (uint32_t)((wm * 64 + (lane & 15)) * 48 + ((lane >> 4) * 8) * 2);
    uint32_t b_off = (uint32_t)((wn * 64 + (lane >> 4) * 8 + (lane & 7)) * 48 +
                                (((lane >> 3) & 1) * 8) * 2);

    float acc[4][8][4];
#pragma unroll
    for (int i = 0; i < 4; i++)
#pragma unroll
        for (int j = 0; j < 8; j++)
#pragma unroll
            for (int q = 0; q < 4; q++) acc[i][j][q] = 0.f;

    const int NC = K / 16;

#define ISSUE(cidx)                                                            \
    do {                                                                       \
        uint32_t bufb = sb + (uint32_t)((cidx) & 3) * STG_SZ;                  \
        int koff = (cidx) * 16;                                                \
        cp_async16(bufb + cpso0,         pAh + koff);                          \
        cp_async16(bufb + cpso1,         pAh + r64 + koff);                    \
        cp_async16(bufb + 6144 + cpso0,  pAl + koff);                          \
        cp_async16(bufb + 6144 + cpso1,  pAl + r64 + koff);                    \
        cp_async16(bufb + 12288 + cpso0, pBh + koff);                          \
        cp_async16(bufb + 12288 + cpso1, pBh + r64 + koff);                    \
        cp_async16(bufb + 18432 + cpso0, pBl + koff);                          \
        cp_async16(bufb + 18432 + cpso1, pBl + r64 + koff);                    \
        CP_COMMIT();                                                           \
    } while (0)

    ISSUE(0);
    ISSUE(1);
    ISSUE(2);

    for (int c = 0; c < NC; ++c) {
        int rem = NC - 1 - c;
        if (rem >= 2)      { CP_WAIT(2); }
        else if (rem == 1) { CP_WAIT(1); }
        else               { CP_WAIT(0); }
        __syncthreads();
        if (c + 3 < NC) ISSUE(c + 3);

        uint32_t base = sb + (uint32_t)(c & 3) * STG_SZ;

        uint32_t BH[4][4], BL[4][4];
#pragma unroll
        for (int p = 0; p < 4; p++) {
            uint32_t bd = base + 12288 + b_off + p * 768;
            ldsm4(BH[p], bd);
            ldsm4(BL[p], bd + 6144);
        }
        uint32_t AHp[2][4], ALp[2][4];
        ldsm4(AHp[0], base + a_off);
        ldsm4(ALp[0], base + a_off + 6144);
#pragma unroll
        for (int mt = 0; mt < 4; mt++) {
            int cur = mt & 1, nxt = cur ^ 1;
            if (mt < 3) {
                uint32_t ad = base + a_off + (mt + 1) * 768;
                ldsm4(AHp[nxt], ad);
                ldsm4(ALp[nxt], ad + 6144);
            }
#pragma unroll
            for (int nt = 0; nt < 8; nt++) {
                const uint32_t* bh = &BH[nt >> 1][(nt & 1) * 2];
                const uint32_t* bl = &BL[nt >> 1][(nt & 1) * 2];
                mma_bf16(acc[mt][nt], AHp[cur], bh);
                mma_bf16(acc[mt][nt], AHp[cur], bl);
                mma_bf16(acc[mt][nt], ALp[cur], bh);
            }
        }
    }

    int g = lane >> 2, tg = lane & 3;
#pragma unroll
    for (int mt = 0; mt < 4; mt++) {
        int row = blockIdx.y * 128 + wm * 64 + mt * 16 + g;
#pragma unroll
        for (int nt = 0; nt < 8; nt++) {
            int col = blockIdx.x * 128 + wn * 64 + nt * 8 + tg * 2;
            *(float2*)(C + (size_t)row * N + col) =
                make_float2(acc[mt][nt][0], acc[mt][nt][1]);
            *(float2*)(C + (size_t)(row + 8) * N + col) =
                make_float2(acc[mt][nt][2], acc[mt][nt][3]);
        }
    }
}

// ---------------------------------------------------------------------------
// RoPE + bf16 hi/lo split of Q,K,V into head-contiguous scratch.
// ---------------------------------------------------------------------------
__device__ __forceinline__ void split_store(float x, __nv_bfloat16* ph, __nv_bfloat16* pl) {
    uint32_t hb = __float_as_uint(x) & 0xffff0000u;
    *(unsigned short*)ph = (unsigned short)(hb >> 16);
    *pl = __float2bfloat16(x - __uint_as_float(hb));
}

__global__ __launch_bounds__(256) void rope_convert() {
    int idx = blockIdx.x * 256 + threadIdx.x;
    int p = idx & 63;
    int h = (idx >> 6) & 15;
    int t = (idx >> 10) & 2047;
    int b = idx >> 21;

    float inv_freq = powf(10000.0f, -(float)p * (1.0f / 64.0f));
    float ang = (float)t * inv_freq;
    float s, c;
    sincosf(ang, &s, &c);

    size_t src = ((size_t)(b * T_SEQ + t)) * QKV_DIM + h * HD + p;
    size_t dst = ((size_t)((b * NH + h) * T_SEQ) + t) * HD + p;

    float q1 = g_qkv[src], q2 = g_qkv[src + 64];
    float qr1 = q1 * c - q2 * s, qr2 = q1 * s + q2 * c;
    split_store(qr1, &g_qh[dst], &g_ql[dst]);
    split_store(qr2, &g_qh[dst + 64], &g_ql[dst + 64]);

    float k1 = g_qkv[src + DIM], k2 = g_qkv[src + DIM + 64];
    float kr1 = k1 * c - k2 * s, kr2 = k1 * s + k2 * c;
    split_store(kr1, &g_kh[dst], &g_kl[dst]);
    split_store(kr2, &g_kh[dst + 64], &g_kl[dst + 64]);

    float v1 = g_qkv[src + 2 * DIM], v2 = g_qkv[src + 2 * DIM + 64];
    split_store(v1, &g_vh[dst], &g_vl[dst]);
    split_store(v2, &g_vh[dst + 64], &g_vl[dst + 64]);
}

// ---------------------------------------------------------------------------
// Tensor-core causal flash attention, BQ=128, cp.async double-buffered K/V.
// One barrier per key tile; fully-masked warps skip compute.
// ---------------------------------------------------------------------------
#define SST 272
#define O_QH 0
#define O_QL 34816
#define O_KH 69632                    // each K/V array: 2 bufs x 17408
#define O_KL (O_KH + 34816)
#define O_VH (O_KL + 34816)
#define O_VL (O_VH + 34816)
#define KVB 17408
#define ATTN_SMEM2 (O_VL + 34816)     // 208896 B

__global__ __launch_bounds__(256) void attn_mma() {
    extern __shared__ char sm[];
    uint32_t sb = smem_u32(sm);
    int tid = threadIdx.x, lane = tid & 31, w = tid >> 5;   // w: 0..7
    int qt = blockIdx.x, hd = blockIdx.y, b = blockIdx.z;
    int q0 = qt * 128;
    size_t hb = ((size_t)(b * NH + hd)) * T_SEQ;

    const char* kh_g = (const char*)(g_kh + hb * HD);
    const char* kl_g = (const char*)(g_kl + hb * HD);
    const char* vh_g = (const char*)(g_vh + hb * HD);
    const char* vl_g = (const char*)(g_vl + hb * HD);

    // load Q hi/lo tile [128][128] bf16 (plain stores; once per CTA)
    {
        const char* qh_g = (const char*)(g_qh + (hb + q0) * HD);
        const char* ql_g = (const char*)(g_ql + (hb + q0) * HD);
#pragma unroll
        for (int i = 0; i < 8; i++) {
            int idx = tid + i * 256;
            int r = idx >> 4, ch = idx & 15;
            int so = r * SST + ch * 16, go = r * 256 + ch * 16;
            *(uint4*)(sm + O_QH + so) = *(const uint4*)(qh_g + go);
            *(uint4*)(sm + O_QL + so) = *(const uint4*)(ql_g + go);
        }
    }

    // K/V cp.async tile issue: 4 chunks of 16B per array per thread
#define KV_ISSUE(ktile)                                                          \
    do {                                                                         \
        uint32_t bo = (uint32_t)((ktile) & 1) * KVB;                             \
        size_t gk0 = (size_t)(ktile) * 64 * 256;                                 \
        _Pragma("unroll")                                                        \
        for (int i_ = 0; i_ < 4; i_++) {                                         \
            int idx_ = tid + i_ * 256;                                           \
            int r_ = idx_ >> 4, ch_ = idx_ & 15;                                 \
            uint32_t so_ = (uint32_t)(r_ * SST + ch_ * 16);                      \
            size_t go_ = gk0 + (size_t)r_ * 256 + ch_ * 16;                      \
            cp_async16(sb + O_KH + bo + so_, kh_g + go_);                        \
            cp_async16(sb + O_KL + bo + so_, kl_g + go_);                        \
            cp_async16(sb + O_VH + bo + so_, vh_g + go_);                        \
            cp_async16(sb + O_VL + bo + so_, vl_g + go_);                        \
        }                                                                        \
        CP_COMMIT();                                                             \
    } while (0)

    KV_ISSUE(0);
    __syncthreads();   // Q tile visible to all warps

    int g = lane >> 2, tg = lane & 3;
    uint32_t q_off = (uint32_t)((w * 16 + (lane & 15)) * SST + ((lane >> 4) * 8) * 2);
    uint32_t kb_off = (uint32_t)((((lane >> 4) * 8) + (lane & 7)) * SST +
                                 (((lane >> 3) & 1) * 8) * 2);
    uint32_t v_off = (uint32_t)((lane & 15) * SST + ((lane >> 4) * 8) * 2);

    // hoist Q fragments into registers
    uint32_t QH[8][4], QL[8][4];
#pragma unroll
    for (int ks = 0; ks < 8; ++ks) {
        ldsm4(QH[ks], sb + O_QH + q_off + ks * 32);
        ldsm4(QL[ks], sb + O_QL + q_off + ks * 32);
    }

    float o[16][4];
#pragma unroll
    for (int i = 0; i < 16; i++)
#pragma unroll
        for (int j = 0; j < 4; j++) o[i][j] = 0.f;

    float m0 = -1e30f, m1 = -1e30f, l0 = 0.f, l1 = 0.f;
    const float scale = 0.08838834764831845f;

    int ktmax = 2 * qt + 1;
    for (int kt = 0; kt <= ktmax; ++kt) {
        int k0 = kt * 64;
        CP_WAIT(0);          // tile kt arrived
        __syncthreads();     // visible everywhere; tile kt-1 reads complete
        if (kt + 1 <= ktmax) KV_ISSUE(kt + 1);   // overlaps this tile's compute

        // fully-masked warp skip (contribution would be p=0, alpha=1)
        if (k0 > q0 + w * 16 + 15) continue;

        uint32_t bo = (uint32_t)(kt & 1) * KVB;

        float st[8][4];
#pragma unroll
        for (int i = 0; i < 8; i++)
#pragma unroll
            for (int j = 0; j < 4; j++) st[i][j] = 0.f;

#pragma unroll
        for (int ks = 0; ks < 8; ++ks) {
#pragma unroll
            for (int p = 0; p < 4; ++p) {
                uint32_t BH4[4], BL4[4];
                uint32_t ko = bo + kb_off + p * 16 * SST + ks * 32;
                ldsm4(BH4, sb + O_KH + ko);
                ldsm4(BL4, sb + O_KL + ko);
                mma_bf16(st[2 * p], QH[ks], BH4);
                mma_bf16(st[2 * p], QH[ks], BL4);
                mma_bf16(st[2 * p], QL[ks], BH4);
                mma_bf16(st[2 * p + 1], QH[ks], BH4 + 2);
                mma_bf16(st[2 * p + 1], QH[ks], BL4 + 2);
                mma_bf16(st[2 * p + 1], QL[ks], BH4 + 2);
            }
        }

        int rowg = q0 + w * 16 + g;
        bool diag = (k0 + 63 > q0 + w * 16);
        float mx0 = -1e30f, mx1 = -1e30f;
#pragma unroll
        for (int nt = 0; nt < 8; ++nt) {
            int c0 = k0 + nt * 8 + 2 * tg;
            st[nt][0] *= scale; st[nt][1] *= scale;
            st[nt][2] *= scale; st[nt][3] *= scale;
            if (diag) {
                if (c0 > rowg)         st[nt][0] = -1e30f;
                if (c0 + 1 > rowg)     st[nt][1] = -1e30f;
                if (c0 > rowg + 8)     st[nt][2] = -1e30f;
                if (c0 + 1 > rowg + 8) st[nt][3] = -1e30f;
            }
            mx0 = fmaxf(mx0, fmaxf(st[nt][0], st[nt][1]));
            mx1 = fmaxf(mx1, fmaxf(st[nt][2], st[nt][3]));
        }
        mx0 = fmaxf(mx0, __shfl_xor_sync(0xffffffffu, mx0, 1));
        mx0 = fmaxf(mx0, __shfl_xor_sync(0xffffffffu, mx0, 2));
        mx1 = fmaxf(mx1, __shfl_xor_sync(0xffffffffu, mx1, 1));
        mx1 = fmaxf(mx1, __shfl_xor_sync(0xffffffffu, mx1, 2));

        float mn0 = fmaxf(m0, mx0), mn1 = fmaxf(m1, mx1);
        float al0 = __expf(m0 - mn0), al1 = __expf(m1 - mn1);
        float s0 = 0.f, s1 = 0.f;
#pragma unroll
        for (int nt = 0; nt < 8; ++nt) {
            st[nt][0] = __expf(st[nt][0] - mn0);
            st[nt][1] = __expf(st[nt][1] - mn0);
            st[nt][2] = __expf(st[nt][2] - mn1);
            st[nt][3] = __expf(st[nt][3] - mn1);
            s0 += st[nt][0] + st[nt][1];
            s1 += st[nt][2] + st[nt][3];
        }
        s0 += __shfl_xor_sync(0xffffffffu, s0, 1);
        s0 += __shfl_xor_sync(0xffffffffu, s0, 2);
        s1 += __shfl_xor_sync(0xffffffffu, s1, 1);
        s1 += __shfl_xor_sync(0xffffffffu, s1, 2);
        l0 = l0 * al0 + s0;
        l1 = l1 * al1 + s1;
        m0 = mn0; m1 = mn1;

#pragma unroll
        for (int i = 0; i < 16; i++) {
            o[i][0] *= al0; o[i][1] *= al0;
            o[i][2] *= al1; o[i][3] *= al1;
        }

#pragma unroll
        for (int ks = 0; ks < 4; ++ks) {
            float e0 = st[2 * ks][0], e1 = st[2 * ks][1];
            float e2 = st[2 * ks][2], e3 = st[2 * ks][3];
            float f0 = st[2 * ks + 1][0], f1 = st[2 * ks + 1][1];
            float f2 = st[2 * ks + 1][2], f3 = st[2 * ks + 1][3];
            uint32_t PH[4], PL[4];
            PH[0] = prmt_hi(e0, e1); PH[1] = prmt_hi(e2, e3);
            PH[2] = prmt_hi(f0, f1); PH[3] = prmt_hi(f2, f3);
            PL[0] = cvt_bf2(e0 - trunc_bf(e0), e1 - trunc_bf(e1));
            PL[1] = cvt_bf2(e2 - trunc_bf(e2), e3 - trunc_bf(e3));
            PL[2] = cvt_bf2(f0 - trunc_bf(f0), f1 - trunc_bf(f1));
            PL[3] = cvt_bf2(f2 - trunc_bf(f2), f3 - trunc_bf(f3));
#pragma unroll
            for (int np = 0; np < 8; ++np) {
                uint32_t VH4[4], VL4[4];
                uint32_t vo = bo + v_off + ks * 16 * SST + np * 32;
                ldsm4t(VH4, sb + O_VH + vo);
                ldsm4t(VL4, sb + O_VL + vo);
                mma_bf16(o[2 * np], PH, VH4);
                mma_bf16(o[2 * np], PL, VH4);
                mma_bf16(o[2 * np], PH, VL4);
                mma_bf16(o[2 * np + 1], PH, VH4 + 2);
                mma_bf16(o[2 * np + 1], PL, VH4 + 2);
                mma_bf16(o[2 * np + 1], PH, VL4 + 2);
            }
        }
    }

    float inv0 = 1.f / l0, inv1 = 1.f / l1;
    int r0 = q0 + w * 16 + g;
    size_t base0 = ((size_t)(b * T_SEQ) + r0) * DIM + hd * HD;
    size_t base1 = base0 + (size_t)8 * DIM;
#pragma unroll
    for (int np = 0; np < 16; ++np) {
        int col = np * 8 + 2 * tg;
        float v0 = o[np][0] * inv0, v1 = o[np][1] * inv0;
        float v2 = o[np][2] * inv1, v3 = o[np][3] * inv1;
        *(uint32_t*)((unsigned short*)g_ath + base0 + col) = prmt_hi(v0, v1);
        *(uint32_t*)((unsigned short*)g_atl + base0 + col) =
            cvt_bf2(v0 - trunc_bf(v0), v1 - trunc_bf(v1));
        *(uint32_t*)((unsigned short*)g_ath + base1 + col) = prmt_hi(v2, v3);
        *(uint32_t*)((unsigned short*)g_atl + base1 + col) =
            cvt_bf2(v2 - trunc_bf(v2), v3 - trunc_bf(v3));
    }
}

// ---------------------------------------------------------------------------
extern "C" void kernel_launch(void* const* d_in, const int* in_sizes, int n_in,
                              void* d_out, int out_size) {
    const float* x     = (const float*)d_in[0];
    const float* w_qkv = (const float*)d_in[1];
    const float* w_out = (const float*)d_in[2];
    float* out = (float*)d_out;

    float* qkv_ptr; cudaGetSymbolAddress((void**)&qkv_ptr, g_qkv);
    __nv_bfloat16 *xh, *xl, *wqh, *wql, *woh, *wol, *ath, *atl;
    cudaGetSymbolAddress((void**)&xh, g_xh);   cudaGetSymbolAddress((void**)&xl, g_xl);
    cudaGetSymbolAddress((void**)&wqh, g_wqh); cudaGetSymbolAddress((void**)&wql, g_wql);
    cudaGetSymbolAddress((void**)&woh, g_woh); cudaGetSymbolAddress((void**)&wol, g_wol);
    cudaGetSymbolAddress((void**)&ath, g_ath); cudaGetSymbolAddress((void**)&atl, g_atl);

    cudaFuncSetAttribute(gemm_presplit, cudaFuncAttributeMaxDynamicSharedMemorySize, GEMM_SMEM);
    cudaFuncSetAttribute(attn_mma, cudaFuncAttributeMaxDynamicSharedMemorySize, ATTN_SMEM2);

    // 0) fused pre-split of x, w_qkv, w_out into bf16 hi/lo
    int total4 = N4_X + N4_WQ + N4_WO;
    split_all<<<(total4 + 255) / 256, 256>>>(x, w_qkv, w_out);

    // 1) QKV projection
    gemm_presplit<<<dim3(QKV_DIM / 128, 4096 / 128), 128, GEMM_SMEM>>>(
        xh, xl, wqh, wql, qkv_ptr, QKV_DIM, DIM);
    // 2) RoPE + bf16 hi/lo split
    rope_convert<<<(2 * T_SEQ * NH * 64) / 256, 256>>>();
    // 3) causal attention (BQ=128, cp.async K/V pipeline)
    attn_mma<<<dim3(T_SEQ / 128, NH, 2), 256, ATTN_SMEM2>>>();
    // 4) output projection
    gemm_presplit<<<dim3(DIM / 128, 4096 / 128), 128, GEMM_SMEM>>>(
        ath, atl, woh, wol, out, DIM, DIM);
}

// round 14
// speedup vs baseline: 1.0237x; 1.0237x over previous
#include <cuda_runtime.h>
#include <cuda_bf16.h>
#include <math.h>
#include <float.h>
#include <stdint.h>

#define T_SEQ 2048
#define NH 16
#define HD 128
#define DIM 2048
#define QKV_DIM 6144

// ---- mma.sync bf16 primitives (base ISA, works at compute_103) ----
__device__ __forceinline__ uint32_t smem_u32(const void* p) {
    uint32_t a;
    asm("{ .reg .u64 t; cvta.to.shared.u64 t, %1; cvt.u32.u64 %0, t; }"
        : "=r"(a) : "l"(p));
    return a;
}
__device__ __forceinline__ void ldsm4(uint32_t* r, uint32_t addr) {
    asm volatile("ldmatrix.sync.aligned.m8n8.x4.shared.b16 {%0,%1,%2,%3}, [%4];"
                 : "=r"(r[0]), "=r"(r[1]), "=r"(r[2]), "=r"(r[3]) : "r"(addr));
}
__device__ __forceinline__ void ldsm4t(uint32_t* r, uint32_t addr) {
    asm volatile("ldmatrix.sync.aligned.m8n8.x4.trans.shared.b16 {%0,%1,%2,%3}, [%4];"
                 : "=r"(r[0]), "=r"(r[1]), "=r"(r[2]), "=r"(r[3]) : "r"(addr));
}
__device__ __forceinline__ void mma_bf16(float* c, const uint32_t* a, const uint32_t* b) {
    asm volatile(
        "mma.sync.aligned.m16n8k16.row.col.f32.bf16.bf16.f32 "
        "{%0,%1,%2,%3}, {%4,%5,%6,%7}, {%8,%9}, {%0,%1,%2,%3};"
        : "+f"(c[0]), "+f"(c[1]), "+f"(c[2]), "+f"(c[3])
        : "r"(a[0]), "r"(a[1]), "r"(a[2]), "r"(a[3]), "r"(b[0]), "r"(b[1]));
}
__device__ __forceinline__ uint32_t prmt_hi(float x, float y) {
    uint32_t r;
    asm("prmt.b32 %0, %1, %2, 0x7632;" : "=r"(r)
        : "r"(__float_as_uint(x)), "r"(__float_as_uint(y)));
    return r;
}
__device__ __forceinline__ float trunc_bf(float v) {
    return __uint_as_float(__float_as_uint(v) & 0xffff0000u);
}
__device__ __forceinline__ uint32_t cvt_bf2(float lo, float hi) {
    uint32_t r;
    asm("cvt.rn.bf16x2.f32 %0, %1, %2;" : "=r"(r) : "f"(hi), "f"(lo));
    return r;
}
__device__ __forceinline__ void cp_async16(uint32_t saddr, const void* gptr) {
    asm volatile("cp.async.cg.shared.global [%0], [%1], 16;" :: "r"(saddr), "l"(gptr));
}
#define CP_COMMIT() asm volatile("cp.async.commit_group;" ::: "memory")
#define CP_WAIT(n)  asm volatile("cp.async.wait_group %0;" :: "n"(n) : "memory")

// ---------------- global scratch (allocation-free rule) ----------------
__device__ float g_qkv[2L * T_SEQ * QKV_DIM];
__device__ __nv_bfloat16 g_xh[4096L * DIM],   g_xl[4096L * DIM];
__device__ __nv_bfloat16 g_wqh[(long)QKV_DIM * DIM], g_wql[(long)QKV_DIM * DIM];
__device__ __nv_bfloat16 g_woh[(long)DIM * DIM],     g_wol[(long)DIM * DIM];
__device__ __nv_bfloat16 g_ath[4096L * DIM],  g_atl[4096L * DIM];
__device__ __nv_bfloat16 g_qh[2L * NH * T_SEQ * HD], g_ql[2L * NH * T_SEQ * HD];
__device__ __nv_bfloat16 g_kh[2L * NH * T_SEQ * HD], g_kl[2L * NH * T_SEQ * HD];
__device__ __nv_bfloat16 g_vh[2L * NH * T_SEQ * HD], g_vl[2L * NH * T_SEQ * HD];

// ---------------------------------------------------------------------------
// fused fp32 -> bf16 hi/lo split for x, w_qkv, w_out (one launch)
// ---------------------------------------------------------------------------
#define N4_X  (4096 * DIM / 4)
#define N4_WQ (QKV_DIM * DIM / 4)
#define N4_WO (DIM * DIM / 4)

__global__ __launch_bounds__(256) void split_all(const float* __restrict__ x,
                                                 const float* __restrict__ wq,
                                                 const float* __restrict__ wo) {
    int i = blockIdx.x * 256 + threadIdx.x;
    const float* src;
    __nv_bfloat16 *dh, *dl;
    int j;
    if (i < N4_X) {
        src = x; dh = g_xh; dl = g_xl; j = i;
    } else if (i < N4_X + N4_WQ) {
        src = wq; dh = g_wqh; dl = g_wql; j = i - N4_X;
    } else if (i < N4_X + N4_WQ + N4_WO) {
        src = wo; dh = g_woh; dl = g_wol; j = i - N4_X - N4_WQ;
    } else return;
    float4 v = ((const float4*)src)[j];
    uint32_t h01 = prmt_hi(v.x, v.y), h23 = prmt_hi(v.z, v.w);
    uint32_t l01 = cvt_bf2(v.x - trunc_bf(v.x), v.y - trunc_bf(v.y));
    uint32_t l23 = cvt_bf2(v.z - trunc_bf(v.z), v.w - trunc_bf(v.w));
    ((uint2*)dh)[j] = make_uint2(h01, h23);
    ((uint2*)dl)[j] = make_uint2(l01, l23);
}

// ---------------------------------------------------------------------------
// Pre-split bf16x3 GEMM, 64x64 warp tiles, 4-stage depth-3 pipeline.
// Split-term MMAs issued term-major across nt (longer RAW spacing on acc).
// ---------------------------------------------------------------------------
#define NSTG 4
#define STG_SZ 24576
#define GEMM_SMEM (NSTG * STG_SZ)   // 98304 B

__global__ __launch_bounds__(128, 2) void gemm_presplit(
    const __nv_bfloat16* __restrict__ Ah, const __nv_bfloat16* __restrict__ Al,
    const __nv_bfloat16* __restrict__ Bh, const __nv_bfloat16* __restrict__ Bl,
    float* __restrict__ C, int N, int K) {
    extern __shared__ char sm[];
    uint32_t sb = smem_u32(sm);
    int tid = threadIdx.x, lane = tid & 31, wid = tid >> 5;
    int wm = wid >> 1, wn = wid & 1;

    size_t arow = (size_t)blockIdx.y * 128;
    size_t brow = (size_t)blockIdx.x * 128;

    int cprow = tid >> 1;
    int half = tid & 1;
    uint32_t cpso0 = (uint32_t)(cprow * 48 + half * 16);
    uint32_t cpso1 = (uint32_t)((cprow + 64) * 48 + half * 16);
    const __nv_bfloat16* pAh = Ah + (arow + cprow) * K + half * 8;
    const __nv_bfloat16* pAl = Al + (arow + cprow) * K + half * 8;
    const __nv_bfloat16* pBh = Bh + (brow + cprow) * K + half * 8;
    const __nv_bfloat16* pBl = Bl + (brow + cprow) * K + half * 8;
    size_t r64 = (size_t)64 * K;

    uint32_t a_off = (uint32_t)((wm * 64 + (lane & 15)) * 48 + ((lane >> 4) * 8) * 2);
    uint32_t b_off = (uint32_t)((wn * 64 + (lane >> 4) * 8 + (lane & 7)) * 48 +
                                (((lane >> 3) & 1) * 8) * 2);

    float acc[4][8][4];
#pragma unroll
    for (int i = 0; i < 4; i++)
#pragma unroll
        for (int j = 0; j < 8; j++)
#pragma unroll
            for (int q = 0; q < 4; q++) acc[i][j][q] = 0.f;

    const int NC = K / 16;

#define ISSUE(cidx)                                                            \
    do {                                                                       \
        uint32_t bufb = sb + (uint32_t)((cidx) & 3) * STG_SZ;                  \
        int koff = (cidx) * 16;                                                \
        cp_async16(bufb + cpso0,         pAh + koff);                          \
        cp_async16(bufb + cpso1,         pAh + r64 + koff);                    \
        cp_async16(bufb + 6144 + cpso0,  pAl + koff);                          \
        cp_async16(bufb + 6144 + cpso1,  pAl + r64 + koff);                    \
        cp_async16(bufb + 12288 + cpso0, pBh + koff);                          \
        cp_async16(bufb + 12288 + cpso1, pBh + r64 + koff);                    \
        cp_async16(bufb + 18432 + cpso0, pBl + koff);                          \
        cp_async16(bufb + 18432 + cpso1, pBl + r64 + koff);                    \
        CP_COMMIT();                                                           \
    } while (0)

    ISSUE(0);
    ISSUE(1);
    ISSUE(2);

    for (int c = 0; c < NC; ++c) {
        int rem = NC - 1 - c;
        if (rem >= 2)      { CP_WAIT(2); }
        else if (rem == 1) { CP_WAIT(1); }
        else               { CP_WAIT(0); }
        __syncthreads();
        if (c + 3 < NC) ISSUE(c + 3);

        uint32_t base = sb + (uint32_t)(c & 3) * STG_SZ;

        uint32_t BH[4][4], BL[4][4];
#pragma unroll
        for (int p = 0; p < 4; p++) {
            uint32_t bd = base + 12288 + b_off + p * 768;
            ldsm4(BH[p], bd);
            ldsm4(BL[p], bd + 6144);
        }
        uint32_t AHp[2][4], ALp[2][4];
        ldsm4(AHp[0], base + a_off);
        ldsm4(ALp[0], base + a_off + 6144);
#pragma unroll
        for (int mt = 0; mt < 4; mt++) {
            int cur = mt & 1, nxt = cur ^ 1;
            if (mt < 3) {
                uint32_t ad = base + a_off + (mt + 1) * 768;
                ldsm4(AHp[nxt], ad);
                ldsm4(ALp[nxt], ad + 6144);
            }
            // term-major: each acc[mt][nt] revisited with 8-instr spacing
#pragma unroll
            for (int nt = 0; nt < 8; nt++)
                mma_bf16(acc[mt][nt], AHp[cur], &BH[nt >> 1][(nt & 1) * 2]);
#pragma unroll
            for (int nt = 0; nt < 8; nt++)
                mma_bf16(acc[mt][nt], AHp[cur], &BL[nt >> 1][(nt & 1) * 2]);
#pragma unroll
            for (int nt = 0; nt < 8; nt++)
                mma_bf16(acc[mt][nt], ALp[cur], &BH[nt >> 1][(nt & 1) * 2]);
        }
    }

    int g = lane >> 2, tg = lane & 3;
#pragma unroll
    for (int mt = 0; mt < 4; mt++) {
        int row = blockIdx.y * 128 + wm * 64 + mt * 16 + g;
#pragma unroll
        for (int nt = 0; nt < 8; nt++) {
            int col = blockIdx.x * 128 + wn * 64 + nt * 8 + tg * 2;
            *(float2*)(C + (size_t)row * N + col) =
                make_float2(acc[mt][nt][0], acc[mt][nt][1]);
            *(float2*)(C + (size_t)(row + 8) * N + col) =
                make_float2(acc[mt][nt][2], acc[mt][nt][3]);
        }
    }
}

// ---------------------------------------------------------------------------
// RoPE + bf16 hi/lo split of Q,K,V into head-contiguous scratch.
// ---------------------------------------------------------------------------
__device__ __forceinline__ void split_store(float x, __nv_bfloat16* ph, __nv_bfloat16* pl) {
    uint32_t hb = __float_as_uint(x) & 0xffff0000u;
    *(unsigned short*)ph = (unsigned short)(hb >> 16);
    *pl = __float2bfloat16(x - __uint_as_float(hb));
}

__global__ __launch_bounds__(256) void rope_convert() {
    int idx = blockIdx.x * 256 + threadIdx.x;
    int p = idx & 63;
    int h = (idx >> 6) & 15;
    int t = (idx >> 10) & 2047;
    int b = idx >> 21;

    float inv_freq = powf(10000.0f, -(float)p * (1.0f / 64.0f));
    float ang = (float)t * inv_freq;
    float s, c;
    sincosf(ang, &s, &c);

    size_t src = ((size_t)(b * T_SEQ + t)) * QKV_DIM + h * HD + p;
    size_t dst = ((size_t)((b * NH + h) * T_SEQ) + t) * HD + p;

    float q1 = g_qkv[src], q2 = g_qkv[src + 64];
    float qr1 = q1 * c - q2 * s, qr2 = q1 * s + q2 * c;
    split_store(qr1, &g_qh[dst], &g_ql[dst]);
    split_store(qr2, &g_qh[dst + 64], &g_ql[dst + 64]);

    float k1 = g_qkv[src + DIM], k2 = g_qkv[src + DIM + 64];
    float kr1 = k1 * c - k2 * s, kr2 = k1 * s + k2 * c;
    split_store(kr1, &g_kh[dst], &g_kl[dst]);
    split_store(kr2, &g_kh[dst + 64], &g_kl[dst + 64]);

    float v1 = g_qkv[src + 2 * DIM], v2 = g_qkv[src + 2 * DIM + 64];
    split_store(v1, &g_vh[dst], &g_vl[dst]);
    split_store(v2, &g_vh[dst + 64], &g_vl[dst + 64]);
}

// ---------------------------------------------------------------------------
// Tensor-core causal flash attention, BQ=64 (R11 config: 2 CTAs/SM),
// Q fragments in registers, bf16x3; epilogue writes bf16 hi/lo directly.
// ---------------------------------------------------------------------------
#define SST 272
#define O_QH 0
#define O_QL 17408
#define O_KH 34816
#define O_KL 52224
#define O_VH 69632
#define O_VL 87040
#define ATTN_SMEM2 104448

__global__ __launch_bounds__(128, 2) void attn_mma() {
    extern __shared__ char sm[];
    uint32_t sb = smem_u32(sm);
    int tid = threadIdx.x, lane = tid & 31, w = tid >> 5;
    int qt = blockIdx.x, hd = blockIdx.y, b = blockIdx.z;
    int q0 = qt * 64;
    size_t hb = ((size_t)(b * NH + hd)) * T_SEQ;

    {
        const char* qh_g = (const char*)(g_qh + (hb + q0) * HD);
        const char* ql_g = (const char*)(g_ql + (hb + q0) * HD);
#pragma unroll
        for (int i = 0; i < 8; i++) {
            int idx = tid + i * 128;
            int r = idx >> 4, ch = idx & 15;
            int so = r * SST + ch * 16, go = r * 256 + ch * 16;
            *(uint4*)(sm + O_QH + so) = *(const uint4*)(qh_g + go);
            *(uint4*)(sm + O_QL + so) = *(const uint4*)(ql_g + go);
        }
    }
    __syncthreads();

    int g = lane >> 2, tg = lane & 3;
    uint32_t q_off = (uint32_t)((w * 16 + (lane & 15)) * SST + ((lane >> 4) * 8) * 2);
    uint32_t kb_off = (uint32_t)((((lane >> 4) * 8) + (lane & 7)) * SST +
                                 (((lane >> 3) & 1) * 8) * 2);
    uint32_t v_off = (uint32_t)((lane & 15) * SST + ((lane >> 4) * 8) * 2);

    // hoist Q fragments (hi/lo) into registers once
    uint32_t QH[8][4], QL[8][4];
#pragma unroll
    for (int ks = 0; ks < 8; ++ks) {
        ldsm4(QH[ks], sb + O_QH + q_off + ks * 32);
        ldsm4(QL[ks], sb + O_QL + q_off + ks * 32);
    }

    float o[16][4];
#pragma unroll
    for (int i = 0; i < 16; i++)
#pragma unroll
        for (int j = 0; j < 4; j++) o[i][j] = 0.f;

    float m0 = -1e30f, m1 = -1e30f, l0 = 0.f, l1 = 0.f;
    const float scale = 0.08838834764831845f;

    for (int kt = 0; kt <= qt; ++kt) {
        int k0 = kt * 64;
        __syncthreads();
        {
            const char* kh_g = (const char*)(g_kh + (hb + k0) * HD);
            const char* kl_g = (const char*)(g_kl + (hb + k0) * HD);
            const char* vh_g = (const char*)(g_vh + (hb + k0) * HD);
            const char* vl_g = (const char*)(g_vl + (hb + k0) * HD);
#pragma unroll
            for (int i = 0; i < 8; i++) {
                int idx = tid + i * 128;
                int r = idx >> 4, ch = idx & 15;
                int so = r * SST + ch * 16, go = r * 256 + ch * 16;
                *(uint4*)(sm + O_KH + so) = *(const uint4*)(kh_g + go);
                *(uint4*)(sm + O_KL + so) = *(const uint4*)(kl_g + go);
                *(uint4*)(sm + O_VH + so) = *(const uint4*)(vh_g + go);
                *(uint4*)(sm + O_VL + so) = *(const uint4*)(vl_g + go);
            }
        }
        __syncthreads();

        float st[8][4];
#pragma unroll
        for (int i = 0; i < 8; i++)
#pragma unroll
            for (int j = 0; j < 4; j++) st[i][j] = 0.f;

#pragma unroll
        for (int ks = 0; ks < 8; ++ks) {
#pragma unroll
            for (int p = 0; p < 4; ++p) {
                uint32_t BH4[4], BL4[4];
                uint32_t ko = kb_off + p * 16 * SST + ks * 32;
                ldsm4(BH4, sb + O_KH + ko);
                ldsm4(BL4, sb + O_KL + ko);
                mma_bf16(st[2 * p], QH[ks], BH4);
                mma_bf16(st[2 * p], QH[ks], BL4);
                mma_bf16(st[2 * p], QL[ks], BH4);
                mma_bf16(st[2 * p + 1], QH[ks], BH4 + 2);
                mma_bf16(st[2 * p + 1], QH[ks], BL4 + 2);
                mma_bf16(st[2 * p + 1], QL[ks], BH4 + 2);
            }
        }

        int rowg = q0 + w * 16 + g;
        bool diag = (kt == qt);
        float mx0 = -1e30f, mx1 = -1e30f;
#pragma unroll
        for (int nt = 0; nt < 8; ++nt) {
            int c0 = k0 + nt * 8 + 2 * tg;
            st[nt][0] *= scale; st[nt][1] *= scale;
            st[nt][2] *= scale; st[nt][3] *= scale;
            if (diag) {
                if (c0 > rowg)         st[nt][0] = -1e30f;
                if (c0 + 1 > rowg)     st[nt][1] = -1e30f;
                if (c0 > rowg + 8)     st[nt][2] = -1e30f;
                if (c0 + 1 > rowg + 8) st[nt][3] = -1e30f;
            }
            mx0 = fmaxf(mx0, fmaxf(st[nt][0], st[nt][1]));
            mx1 = fmaxf(mx1, fmaxf(st[nt][2], st[nt][3]));
        }
        mx0 = fmaxf(mx0, __shfl_xor_sync(0xffffffffu, mx0, 1));
        mx0 = fmaxf(mx0, __shfl_xor_sync(0xffffffffu, mx0, 2));
        mx1 = fmaxf(mx1, __shfl_xor_sync(0xffffffffu, mx1, 1));
        mx1 = fmaxf(mx1, __shfl_xor_sync(0xffffffffu, mx1, 2));

        float mn0 = fmaxf(m0, mx0), mn1 = fmaxf(m1, mx1);
        float al0 = __expf(m0 - mn0), al1 = __expf(m1 - mn1);
        float s0 = 0.f, s1 = 0.f;
#pragma unroll
        for (int nt = 0; nt < 8; ++nt) {
            st[nt][0] = __expf(st[nt][0] - mn0);
            st[nt][1] = __expf(st[nt][1] - mn0);
            st[nt][2] = __expf(st[nt][2] - mn1);
            st[nt][3] = __expf(st[nt][3] - mn1);
            s0 += st[nt][0] + st[nt][1];
            s1 += st[nt][2] + st[nt][3];
        }
        s0 += __shfl_xor_sync(0xffffffffu, s0, 1);
        s0 += __shfl_xor_sync(0xffffffffu, s0, 2);
        s1 += __shfl_xor_sync(0xffffffffu, s1, 1);
        s1 += __shfl_xor_sync(0xffffffffu, s1, 2);
        l0 = l0 * al0 + s0;
        l1 = l1 * al1 + s1;
        m0 = mn0; m1 = mn1;

#pragma unroll
        for (int i = 0; i < 16; i++) {
            o[i][0] *= al0; o[i][1] *= al0;
            o[i][2] *= al1; o[i][3] *= al1;
        }

#pragma unroll
        for (int ks = 0; ks < 4; ++ks) {
            float e0 = st[2 * ks][0], e1 = st[2 * ks][1];
            float e2 = st[2 * ks][2], e3 = st[2 * ks][3];
            float f0 = st[2 * ks + 1][0], f1 = st[2 * ks + 1][1];
            float f2 = st[2 * ks + 1][2], f3 = st[2 * ks + 1][3];
            uint32_t PH[4], PL[4];
            PH[0] = prmt_hi(e0, e1); PH[1] = prmt_hi(e2, e3);
            PH[2] = prmt_hi(f0, f1); PH[3] = prmt_hi(f2, f3);
            PL[0] = cvt_bf2(e0 - trunc_bf(e0), e1 - trunc_bf(e1));
            PL[1] = cvt_bf2(e2 - trunc_bf(e2), e3 - trunc_bf(e3));
            PL[2] = cvt_bf2(f0 - trunc_bf(f0), f1 - trunc_bf(f1));
            PL[3] = cvt_bf2(f2 - trunc_bf(f2), f3 - trunc_bf(f3));
#pragma unroll
            for (int np = 0; np < 8; ++np) {
                uint32_t VH4[4], VL4[4];
                uint32_t vo = v_off + ks * 16 * SST + np * 32;
                ldsm4t(VH4, sb + O_VH + vo);
                ldsm4t(VL4, sb + O_VL + vo);
                mma_bf16(o[2 * np], PH, VH4);
                mma_bf16(o[2 * np], PL, VH4);
                mma_bf16(o[2 * np], PH, VL4);
                mma_bf16(o[2 * np + 1], PH, VH4 + 2);
                mma_bf16(o[2 * np + 1], PL, VH4 + 2);
                mma_bf16(o[2 * np + 1], PH, VL4 + 2);
            }
        }
    }

    float inv0 = 1.f / l0, inv1 = 1.f / l1;
    int r0 = q0 + w * 16 + g;
    size_t base0 = ((size_t)(b * T_SEQ) + r0) * DIM + hd * HD;
    size_t base1 = base0 + (size_t)8 * DIM;
#pragma unroll
    for (int np = 0; np < 16; ++np) {
        int col = np * 8 + 2 * tg;
        float v0 = o[np][0] * inv0, v1 = o[np][1] * inv0;
        float v2 = o[np][2] * inv1, v3 = o[np][3] * inv1;
        *(uint32_t*)((unsigned short*)g_ath + base0 + col) = prmt_hi(v0, v1);
        *(uint32_t*)((unsigned short*)g_atl + base0 + col) =
            cvt_bf2(v0 - trunc_bf(v0), v1 - trunc_bf(v1));
        *(uint32_t*)((unsigned short*)g_ath + base1 + col) = prmt_hi(v2, v3);
        *(uint32_t*)((unsigned short*)g_atl + base1 + col) =
            cvt_bf2(v2 - trunc_bf(v2), v3 - trunc_bf(v3));
    }
}

// ---------------------------------------------------------------------------
extern "C" void kernel_launch(void* const* d_in, const int* in_sizes, int n_in,
                              void* d_out, int out_size) {
    const float* x     = (const float*)d_in[0];
    const float* w_qkv = (const float*)d_in[1];
    const float* w_out = (const float*)d_in[2];
    float* out = (float*)d_out;

    float* qkv_ptr; cudaGetSymbolAddress((void**)&qkv_ptr, g_qkv);
    __nv_bfloat16 *xh, *xl, *wqh, *wql, *woh, *wol, *ath, *atl;
    cudaGetSymbolAddress((void**)&xh, g_xh);   cudaGetSymbolAddress((void**)&xl, g_xl);
    cudaGetSymbolAddress((void**)&wqh, g_wqh); cudaGetSymbolAddress((void**)&wql, g_wql);
    cudaGetSymbolAddress((void**)&woh, g_woh); cudaGetSymbolAddress((void**)&wol, g_wol);
    cudaGetSymbolAddress((void**)&ath, g_ath); cudaGetSymbolAddress((void**)&atl, g_atl);

    cudaFuncSetAttribute(gemm_presplit, cudaFuncAttributeMaxDynamicSharedMemorySize, GEMM_SMEM);
    cudaFuncSetAttribute(attn_mma, cudaFuncAttributeMaxDynamicSharedMemorySize, ATTN_SMEM2);

    // 0) fused pre-split of x, w_qkv, w_out into bf16 hi/lo
    int total4 = N4_X + N4_WQ + N4_WO;
    split_all<<<(total4 + 255) / 256, 256>>>(x, w_qkv, w_out);

    // 1) QKV projection
    gemm_presplit<<<dim3(QKV_DIM / 128, 4096 / 128), 128, GEMM_SMEM>>>(
        xh, xl, wqh, wql, qkv_ptr, QKV_DIM, DIM);
    // 2) RoPE + bf16 hi/lo split
    rope_convert<<<(2 * T_SEQ * NH * 64) / 256, 256>>>();
    // 3) causal attention (BQ=64, 2 CTAs/SM)
    attn_mma<<<dim3(T_SEQ / 64, NH, 2), 128, ATTN_SMEM2>>>();
    // 4) output projection
    gemm_presplit<<<dim3(DIM / 128, 4096 / 128), 128, GEMM_SMEM>>>(
        ath, atl, woh, wol, out, DIM, DIM);
}

// round 15
// speedup vs baseline: 1.2893x; 1.2595x over previous
#include <cuda_runtime.h>
#include <cuda_bf16.h>
#include <cuda_fp16.h>
#include <math.h>
#include <float.h>
#include <stdint.h>

#define T_SEQ 2048
#define NH 16
#define HD 128
#define DIM 2048
#define QKV_DIM 6144

// ---- mma.sync primitives (base ISA, works at compute_103) ----
__device__ __forceinline__ uint32_t smem_u32(const void* p) {
    uint32_t a;
    asm("{ .reg .u64 t; cvta.to.shared.u64 t, %1; cvt.u32.u64 %0, t; }"
        : "=r"(a) : "l"(p));
    return a;
}
__device__ __forceinline__ void ldsm4(uint32_t* r, uint32_t addr) {
    asm volatile("ldmatrix.sync.aligned.m8n8.x4.shared.b16 {%0,%1,%2,%3}, [%4];"
                 : "=r"(r[0]), "=r"(r[1]), "=r"(r[2]), "=r"(r[3]) : "r"(addr));
}
__device__ __forceinline__ void ldsm4t(uint32_t* r, uint32_t addr) {
    asm volatile("ldmatrix.sync.aligned.m8n8.x4.trans.shared.b16 {%0,%1,%2,%3}, [%4];"
                 : "=r"(r[0]), "=r"(r[1]), "=r"(r[2]), "=r"(r[3]) : "r"(addr));
}
__device__ __forceinline__ void mma_bf16(float* c, const uint32_t* a, const uint32_t* b) {
    asm volatile(
        "mma.sync.aligned.m16n8k16.row.col.f32.bf16.bf16.f32 "
        "{%0,%1,%2,%3}, {%4,%5,%6,%7}, {%8,%9}, {%0,%1,%2,%3};"
        : "+f"(c[0]), "+f"(c[1]), "+f"(c[2]), "+f"(c[3])
        : "r"(a[0]), "r"(a[1]), "r"(a[2]), "r"(a[3]), "r"(b[0]), "r"(b[1]));
}
__device__ __forceinline__ void mma_f16(float* c, const uint32_t* a, const uint32_t* b) {
    asm volatile(
        "mma.sync.aligned.m16n8k16.row.col.f32.f16.f16.f32 "
        "{%0,%1,%2,%3}, {%4,%5,%6,%7}, {%8,%9}, {%0,%1,%2,%3};"
        : "+f"(c[0]), "+f"(c[1]), "+f"(c[2]), "+f"(c[3])
        : "r"(a[0]), "r"(a[1]), "r"(a[2]), "r"(a[3]), "r"(b[0]), "r"(b[1]));
}
__device__ __forceinline__ uint32_t prmt_hi(float x, float y) {
    uint32_t r;
    asm("prmt.b32 %0, %1, %2, 0x7632;" : "=r"(r)
        : "r"(__float_as_uint(x)), "r"(__float_as_uint(y)));
    return r;
}
__device__ __forceinline__ float trunc_bf(float v) {
    return __uint_as_float(__float_as_uint(v) & 0xffff0000u);
}
__device__ __forceinline__ uint32_t cvt_bf2(float lo, float hi) {
    uint32_t r;
    asm("cvt.rn.bf16x2.f32 %0, %1, %2;" : "=r"(r) : "f"(hi), "f"(lo));
    return r;
}
__device__ __forceinline__ void cp_async16(uint32_t saddr, const void* gptr) {
    asm volatile("cp.async.cg.shared.global [%0], [%1], 16;" :: "r"(saddr), "l"(gptr));
}
#define CP_COMMIT() asm volatile("cp.async.commit_group;" ::: "memory")
#define CP_WAIT(n)  asm volatile("cp.async.wait_group %0;" :: "n"(n) : "memory")

// fp16 2-term split of a float pair -> (hi half2, lo half2)
__device__ __forceinline__ void f16_split2(float x, float y, __half2* h, __half2* l) {
    __half2 hh = __floats2half2_rn(x, y);
    float rx = x - __half2float(__low2half(hh));
    float ry = y - __half2float(__high2half(hh));
    *h = hh;
    *l = __floats2half2_rn(rx, ry);
}

// ---------------- global scratch (allocation-free rule) ----------------
__device__ float g_qkv[2L * T_SEQ * QKV_DIM];
// fp16 2-term activations + single-rounded fp16 weights
__device__ __half g_xh[4096L * DIM],  g_xl[4096L * DIM];
__device__ __half g_wq1[(long)QKV_DIM * DIM];
__device__ __half g_wo1[(long)DIM * DIM];
__device__ __half g_ath[4096L * DIM], g_atl[4096L * DIM];
// bf16 hi/lo q/k/v for attention (unchanged bf16x3 path)
__device__ __nv_bfloat16 g_qh[2L * NH * T_SEQ * HD], g_ql[2L * NH * T_SEQ * HD];
__device__ __nv_bfloat16 g_kh[2L * NH * T_SEQ * HD], g_kl[2L * NH * T_SEQ * HD];
__device__ __nv_bfloat16 g_vh[2L * NH * T_SEQ * HD], g_vl[2L * NH * T_SEQ * HD];

// ---------------------------------------------------------------------------
// fused pre-convert: x -> fp16 hi/lo, w_qkv/w_out -> single fp16 (one launch)
// ---------------------------------------------------------------------------
#define N4_X  (4096 * DIM / 4)
#define N4_WQ (QKV_DIM * DIM / 4)
#define N4_WO (DIM * DIM / 4)

__global__ __launch_bounds__(256) void split_all(const float* __restrict__ x,
                                                 const float* __restrict__ wq,
                                                 const float* __restrict__ wo) {
    int i = blockIdx.x * 256 + threadIdx.x;
    if (i < N4_X) {
        float4 v = ((const float4*)x)[i];
        __half2 h0, l0, h1, l1;
        f16_split2(v.x, v.y, &h0, &l0);
        f16_split2(v.z, v.w, &h1, &l1);
        ((__half2*)g_xh)[i * 2]     = h0;
        ((__half2*)g_xh)[i * 2 + 1] = h1;
        ((__half2*)g_xl)[i * 2]     = l0;
        ((__half2*)g_xl)[i * 2 + 1] = l1;
    } else if (i < N4_X + N4_WQ) {
        int j = i - N4_X;
        float4 v = ((const float4*)wq)[j];
        ((__half2*)g_wq1)[j * 2]     = __floats2half2_rn(v.x, v.y);
        ((__half2*)g_wq1)[j * 2 + 1] = __floats2half2_rn(v.z, v.w);
    } else if (i < N4_X + N4_WQ + N4_WO) {
        int j = i - N4_X - N4_WQ;
        float4 v = ((const float4*)wo)[j];
        ((__half2*)g_wo1)[j * 2]     = __floats2half2_rn(v.x, v.y);
        ((__half2*)g_wo1)[j * 2 + 1] = __floats2half2_rn(v.z, v.w);
    }
}

// ---------------------------------------------------------------------------
// fp16 2-term GEMM: C = (Ah+Al) * B1^T. 64x64 warp tiles, 4 warps,
// 4-stage depth-3 cp.async pipeline (R11/R14 proven skeleton).
// smem stage: Ah(6144) Al(6144) B1(6144) = 18432 B; rows 48 B.
// ---------------------------------------------------------------------------
#define NSTG 4
#define STG_SZ 18432
#define GEMM_SMEM (NSTG * STG_SZ)   // 73728 B

__global__ __launch_bounds__(128, 2) void gemm_f16_2t(
    const __half* __restrict__ Ah, const __half* __restrict__ Al,
    const __half* __restrict__ B1,
    float* __restrict__ C, int N, int K) {
    extern __shared__ char sm[];
    uint32_t sb = smem_u32(sm);
    int tid = threadIdx.x, lane = tid & 31, wid = tid >> 5;
    int wm = wid >> 1, wn = wid & 1;

    size_t arow = (size_t)blockIdx.y * 128;
    size_t brow = (size_t)blockIdx.x * 128;

    int cprow = tid >> 1;
    int half = tid & 1;
    uint32_t cpso0 = (uint32_t)(cprow * 48 + half * 16);
    uint32_t cpso1 = (uint32_t)((cprow + 64) * 48 + half * 16);
    const __half* pAh = Ah + (arow + cprow) * K + half * 8;
    const __half* pAl = Al + (arow + cprow) * K + half * 8;
    const __half* pB1 = B1 + (brow + cprow) * K + half * 8;
    size_t r64 = (size_t)64 * K;

    uint32_t a_off = (uint32_t)((wm * 64 + (lane & 15)) * 48 + ((lane >> 4) * 8) * 2);
    uint32_t b_off = (uint32_t)((wn * 64 + (lane >> 4) * 8 + (lane & 7)) * 48 +
                                (((lane >> 3) & 1) * 8) * 2);

    float acc[4][8][4];
#pragma unroll
    for (int i = 0; i < 4; i++)
#pragma unroll
        for (int j = 0; j < 8; j++)
#pragma unroll
            for (int q = 0; q < 4; q++) acc[i][j][q] = 0.f;

    const int NC = K / 16;

#define ISSUE(cidx)                                                            \
    do {                                                                       \
        uint32_t bufb = sb + (uint32_t)((cidx) & 3) * STG_SZ;                  \
        int koff = (cidx) * 16;                                                \
        cp_async16(bufb + cpso0,         pAh + koff);                          \
        cp_async16(bufb + cpso1,         pAh + r64 + koff);                    \
        cp_async16(bufb + 6144 + cpso0,  pAl + koff);                          \
        cp_async16(bufb + 6144 + cpso1,  pAl + r64 + koff);                    \
        cp_async16(bufb + 12288 + cpso0, pB1 + koff);                          \
        cp_async16(bufb + 12288 + cpso1, pB1 + r64 + koff);                    \
        CP_COMMIT();                                                           \
    } while (0)

    ISSUE(0);
    ISSUE(1);
    ISSUE(2);

    for (int c = 0; c < NC; ++c) {
        int rem = NC - 1 - c;
        if (rem >= 2)      { CP_WAIT(2); }
        else if (rem == 1) { CP_WAIT(1); }
        else               { CP_WAIT(0); }
        __syncthreads();
        if (c + 3 < NC) ISSUE(c + 3);

        uint32_t base = sb + (uint32_t)(c & 3) * STG_SZ;

        uint32_t BF[4][4];
#pragma unroll
        for (int p = 0; p < 4; p++)
            ldsm4(BF[p], base + 12288 + b_off + p * 768);

        uint32_t AHp[2][4], ALp[2][4];
        ldsm4(AHp[0], base + a_off);
        ldsm4(ALp[0], base + a_off + 6144);
#pragma unroll
        for (int mt = 0; mt < 4; mt++) {
            int cur = mt & 1, nxt = cur ^ 1;
            if (mt < 3) {
                uint32_t ad = base + a_off + (mt + 1) * 768;
                ldsm4(AHp[nxt], ad);
                ldsm4(ALp[nxt], ad + 6144);
            }
            // term-major: Ah pass, then Al pass (8-instr RAW spacing per acc)
#pragma unroll
            for (int nt = 0; nt < 8; nt++)
                mma_f16(acc[mt][nt], AHp[cur], &BF[nt >> 1][(nt & 1) * 2]);
#pragma unroll
            for (int nt = 0; nt < 8; nt++)
                mma_f16(acc[mt][nt], ALp[cur], &BF[nt >> 1][(nt & 1) * 2]);
        }
    }

    int g = lane >> 2, tg = lane & 3;
#pragma unroll
    for (int mt = 0; mt < 4; mt++) {
        int row = blockIdx.y * 128 + wm * 64 + mt * 16 + g;
#pragma unroll
        for (int nt = 0; nt < 8; nt++) {
            int col = blockIdx.x * 128 + wn * 64 + nt * 8 + tg * 2;
            *(float2*)(C + (size_t)row * N + col) =
                make_float2(acc[mt][nt][0], acc[mt][nt][1]);
            *(float2*)(C + (size_t)(row + 8) * N + col) =
                make_float2(acc[mt][nt][2], acc[mt][nt][3]);
        }
    }
}

// ---------------------------------------------------------------------------
// RoPE + bf16 hi/lo split of Q,K,V into head-contiguous scratch. (unchanged)
// ---------------------------------------------------------------------------
__device__ __forceinline__ void split_store(float x, __nv_bfloat16* ph, __nv_bfloat16* pl) {
    uint32_t hb = __float_as_uint(x) & 0xffff0000u;
    *(unsigned short*)ph = (unsigned short)(hb >> 16);
    *pl = __float2bfloat16(x - __uint_as_float(hb));
}

__global__ __launch_bounds__(256) void rope_convert() {
    int idx = blockIdx.x * 256 + threadIdx.x;
    int p = idx & 63;
    int h = (idx >> 6) & 15;
    int t = (idx >> 10) & 2047;
    int b = idx >> 21;

    float inv_freq = powf(10000.0f, -(float)p * (1.0f / 64.0f));
    float ang = (float)t * inv_freq;
    float s, c;
    sincosf(ang, &s, &c);

    size_t src = ((size_t)(b * T_SEQ + t)) * QKV_DIM + h * HD + p;
    size_t dst = ((size_t)((b * NH + h) * T_SEQ) + t) * HD + p;

    float q1 = g_qkv[src], q2 = g_qkv[src + 64];
    float qr1 = q1 * c - q2 * s, qr2 = q1 * s + q2 * c;
    split_store(qr1, &g_qh[dst], &g_ql[dst]);
    split_store(qr2, &g_qh[dst + 64], &g_ql[dst + 64]);

    float k1 = g_qkv[src + DIM], k2 = g_qkv[src + DIM + 64];
    float kr1 = k1 * c - k2 * s, kr2 = k1 * s + k2 * c;
    split_store(kr1, &g_kh[dst], &g_kl[dst]);
    split_store(kr2, &g_kh[dst + 64], &g_kl[dst + 64]);

    float v1 = g_qkv[src + 2 * DIM], v2 = g_qkv[src + 2 * DIM + 64];
    split_store(v1, &g_vh[dst], &g_vl[dst]);
    split_store(v2, &g_vh[dst + 64], &g_vl[dst + 64]);
}

// ---------------------------------------------------------------------------
// Tensor-core causal flash attention, BQ=64 (R14 best config), bf16x3.
// Epilogue writes fp16 2-term (hi/lo) for the fp16 out-projection.
// ---------------------------------------------------------------------------
#define SST 272
#define O_QH 0
#define O_QL 17408
#define O_KH 34816
#define O_KL 52224
#define O_VH 69632
#define O_VL 87040
#define ATTN_SMEM2 104448

__global__ __launch_bounds__(128, 2) void attn_mma() {
    extern __shared__ char sm[];
    uint32_t sb = smem_u32(sm);
    int tid = threadIdx.x, lane = tid & 31, w = tid >> 5;
    int qt = blockIdx.x, hd = blockIdx.y, b = blockIdx.z;
    int q0 = qt * 64;
    size_t hb = ((size_t)(b * NH + hd)) * T_SEQ;

    {
        const char* qh_g = (const char*)(g_qh + (hb + q0) * HD);
        const char* ql_g = (const char*)(g_ql + (hb + q0) * HD);
#pragma unroll
        for (int i = 0; i < 8; i++) {
            int idx = tid + i * 128;
            int r = idx >> 4, ch = idx & 15;
            int so = r * SST + ch * 16, go = r * 256 + ch * 16;
            *(uint4*)(sm + O_QH + so) = *(const uint4*)(qh_g + go);
            *(uint4*)(sm + O_QL + so) = *(const uint4*)(ql_g + go);
        }
    }
    __syncthreads();

    int g = lane >> 2, tg = lane & 3;
    uint32_t q_off = (uint32_t)((w * 16 + (lane & 15)) * SST + ((lane >> 4) * 8) * 2);
    uint32_t kb_off = (uint32_t)((((lane >> 4) * 8) + (lane & 7)) * SST +
                                 (((lane >> 3) & 1) * 8) * 2);
    uint32_t v_off = (uint32_t)((lane & 15) * SST + ((lane >> 4) * 8) * 2);

    uint32_t QH[8][4], QL[8][4];
#pragma unroll
    for (int ks = 0; ks < 8; ++ks) {
        ldsm4(QH[ks], sb + O_QH + q_off + ks * 32);
        ldsm4(QL[ks], sb + O_QL + q_off + ks * 32);
    }

    float o[16][4];
#pragma unroll
    for (int i = 0; i < 16; i++)
#pragma unroll
        for (int j = 0; j < 4; j++) o[i][j] = 0.f;

    float m0 = -1e30f, m1 = -1e30f, l0 = 0.f, l1 = 0.f;
    const float scale = 0.08838834764831845f;

    for (int kt = 0; kt <= qt; ++kt) {
        int k0 = kt * 64;
        __syncthreads();
        {
            const char* kh_g = (const char*)(g_kh + (hb + k0) * HD);
            const char* kl_g = (const char*)(g_kl + (hb + k0) * HD);
            const char* vh_g = (const char*)(g_vh + (hb + k0) * HD);
            const char* vl_g = (const char*)(g_vl + (hb + k0) * HD);
#pragma unroll
            for (int i = 0; i < 8; i++) {
                int idx = tid + i * 128;
                int r = idx >> 4, ch = idx & 15;
                int so = r * SST + ch * 16, go = r * 256 + ch * 16;
                *(uint4*)(sm + O_KH + so) = *(const uint4*)(kh_g + go);
                *(uint4*)(sm + O_KL + so) = *(const uint4*)(kl_g + go);
                *(uint4*)(sm + O_VH + so) = *(const uint4*)(vh_g + go);
                *(uint4*)(sm + O_VL + so) = *(const uint4*)(vl_g + go);
            }
        }
        __syncthreads();

        float st[8][4];
#pragma unroll
        for (int i = 0; i < 8; i++)
#pragma unroll
            for (int j = 0; j < 4; j++) st[i][j] = 0.f;

#pragma unroll
        for (int ks = 0; ks < 8; ++ks) {
#pragma unroll
            for (int p = 0; p < 4; ++p) {
                uint32_t BH4[4], BL4[4];
                uint32_t ko = kb_off + p * 16 * SST + ks * 32;
                ldsm4(BH4, sb + O_KH + ko);
                ldsm4(BL4, sb + O_KL + ko);
                mma_bf16(st[2 * p], QH[ks], BH4);
                mma_bf16(st[2 * p], QH[ks], BL4);
                mma_bf16(st[2 * p], QL[ks], BH4);
                mma_bf16(st[2 * p + 1], QH[ks], BH4 + 2);
                mma_bf16(st[2 * p + 1], QH[ks], BL4 + 2);
                mma_bf16(st[2 * p + 1], QL[ks], BH4 + 2);
            }
        }

        int rowg = q0 + w * 16 + g;
        bool diag = (kt == qt);
        float mx0 = -1e30f, mx1 = -1e30f;
#pragma unroll
        for (int nt = 0; nt < 8; ++nt) {
            int c0 = k0 + nt * 8 + 2 * tg;
            st[nt][0] *= scale; st[nt][1] *= scale;
            st[nt][2] *= scale; st[nt][3] *= scale;
            if (diag) {
                if (c0 > rowg)         st[nt][0] = -1e30f;
                if (c0 + 1 > rowg)     st[nt][1] = -1e30f;
                if (c0 > rowg + 8)     st[nt][2] = -1e30f;
                if (c0 + 1 > rowg + 8) st[nt][3] = -1e30f;
            }
            mx0 = fmaxf(mx0, fmaxf(st[nt][0], st[nt][1]));
            mx1 = fmaxf(mx1, fmaxf(st[nt][2], st[nt][3]));
        }
        mx0 = fmaxf(mx0, __shfl_xor_sync(0xffffffffu, mx0, 1));
        mx0 = fmaxf(mx0, __shfl_xor_sync(0xffffffffu, mx0, 2));
        mx1 = fmaxf(mx1, __shfl_xor_sync(0xffffffffu, mx1, 1));
        mx1 = fmaxf(mx1, __shfl_xor_sync(0xffffffffu, mx1, 2));

        float mn0 = fmaxf(m0, mx0), mn1 = fmaxf(m1, mx1);
        float al0 = __expf(m0 - mn0), al1 = __expf(m1 - mn1);
        float s0 = 0.f, s1 = 0.f;
#pragma unroll
        for (int nt = 0; nt < 8; ++nt) {
            st[nt][0] = __expf(st[nt][0] - mn0);
            st[nt][1] = __expf(st[nt][1] - mn0);
            st[nt][2] = __expf(st[nt][2] - mn1);
            st[nt][3] = __expf(st[nt][3] - mn1);
            s0 += st[nt][0] + st[nt][1];
            s1 += st[nt][2] + st[nt][3];
        }
        s0 += __shfl_xor_sync(0xffffffffu, s0, 1);
        s0 += __shfl_xor_sync(0xffffffffu, s0, 2);
        s1 += __shfl_xor_sync(0xffffffffu, s1, 1);
        s1 += __shfl_xor_sync(0xffffffffu, s1, 2);
        l0 = l0 * al0 + s0;
        l1 = l1 * al1 + s1;
        m0 = mn0; m1 = mn1;

#pragma unroll
        for (int i = 0; i < 16; i++) {
            o[i][0] *= al0; o[i][1] *= al0;
            o[i][2] *= al1; o[i][3] *= al1;
        }

#pragma unroll
        for (int ks = 0; ks < 4; ++ks) {
            float e0 = st[2 * ks][0], e1 = st[2 * ks][1];
            float e2 = st[2 * ks][2], e3 = st[2 * ks][3];
            float f0 = st[2 * ks + 1][0], f1 = st[2 * ks + 1][1];
            float f2 = st[2 * ks + 1][2], f3 = st[2 * ks + 1][3];
            uint32_t PH[4], PL[4];
            PH[0] = prmt_hi(e0, e1); PH[1] = prmt_hi(e2, e3);
            PH[2] = prmt_hi(f0, f1); PH[3] = prmt_hi(f2, f3);
            PL[0] = cvt_bf2(e0 - trunc_bf(e0), e1 - trunc_bf(e1));
            PL[1] = cvt_bf2(e2 - trunc_bf(e2), e3 - trunc_bf(e3));
            PL[2] = cvt_bf2(f0 - trunc_bf(f0), f1 - trunc_bf(f1));
            PL[3] = cvt_bf2(f2 - trunc_bf(f2), f3 - trunc_bf(f3));
#pragma unroll
            for (int np = 0; np < 8; ++np) {
                uint32_t VH4[4], VL4[4];
                uint32_t vo = v_off + ks * 16 * SST + np * 32;
                ldsm4t(VH4, sb + O_VH + vo);
                ldsm4t(VL4, sb + O_VL + vo);
                mma_bf16(o[2 * np], PH, VH4);
                mma_bf16(o[2 * np], PL, VH4);
                mma_bf16(o[2 * np], PH, VL4);
                mma_bf16(o[2 * np + 1], PH, VH4 + 2);
                mma_bf16(o[2 * np + 1], PL, VH4 + 2);
                mma_bf16(o[2 * np + 1], PH, VL4 + 2);
            }
        }
    }

    // finalize: write fp16 2-term split for the out-projection
    float inv0 = 1.f / l0, inv1 = 1.f / l1;
    int r0 = q0 + w * 16 + g;
    size_t base0 = ((size_t)(b * T_SEQ) + r0) * DIM + hd * HD;
    size_t base1 = base0 + (size_t)8 * DIM;
#pragma unroll
    for (int np = 0; np < 16; ++np) {
        int col = np * 8 + 2 * tg;
        float v0 = o[np][0] * inv0, v1 = o[np][1] * inv0;
        float v2 = o[np][2] * inv1, v3 = o[np][3] * inv1;
        __half2 h, l;
        f16_split2(v0, v1, &h, &l);
        *(__half2*)(g_ath + base0 + col) = h;
        *(__half2*)(g_atl + base0 + col) = l;
        f16_split2(v2, v3, &h, &l);
        *(__half2*)(g_ath + base1 + col) = h;
        *(__half2*)(g_atl + base1 + col) = l;
    }
}

// ---------------------------------------------------------------------------
extern "C" void kernel_launch(void* const* d_in, const int* in_sizes, int n_in,
                              void* d_out, int out_size) {
    const float* x     = (const float*)d_in[0];
    const float* w_qkv = (const float*)d_in[1];
    const float* w_out = (const float*)d_in[2];
    float* out = (float*)d_out;

    float* qkv_ptr; cudaGetSymbolAddress((void**)&qkv_ptr, g_qkv);
    __half *xh, *xl, *wq1, *wo1, *ath, *atl;
    cudaGetSymbolAddress((void**)&xh, g_xh);   cudaGetSymbolAddress((void**)&xl, g_xl);
    cudaGetSymbolAddress((void**)&wq1, g_wq1); cudaGetSymbolAddress((void**)&wo1, g_wo1);
    cudaGetSymbolAddress((void**)&ath, g_ath); cudaGetSymbolAddress((void**)&atl, g_atl);

    cudaFuncSetAttribute(gemm_f16_2t, cudaFuncAttributeMaxDynamicSharedMemorySize, GEMM_SMEM);
    cudaFuncSetAttribute(attn_mma, cudaFuncAttributeMaxDynamicSharedMemorySize, ATTN_SMEM2);

    // 0) fused pre-convert
    int total4 = N4_X + N4_WQ + N4_WO;
    split_all<<<(total4 + 255) / 256, 256>>>(x, w_qkv, w_out);

    // 1) QKV projection (fp16 2-term)
    gemm_f16_2t<<<dim3(QKV_DIM / 128, 4096 / 128), 128, GEMM_SMEM>>>(
        xh, xl, wq1, qkv_ptr, QKV_DIM, DIM);
    // 2) RoPE + bf16 hi/lo split
    rope_convert<<<(2 * T_SEQ * NH * 64) / 256, 256>>>();
    // 3) causal attention (BQ=64, bf16x3, 2 CTAs/SM)
    attn_mma<<<dim3(T_SEQ / 64, NH, 2), 128, ATTN_SMEM2>>>();
    // 4) output projection (fp16 2-term)
    gemm_f16_2t<<<dim3(DIM / 128, 4096 / 128), 128, GEMM_SMEM>>>(
        ath, atl, wo1, out, DIM, DIM);
}

// round 17
// speedup vs baseline: 1.4340x; 1.1122x over previous
#include <cuda_runtime.h>
#include <cuda_fp16.h>
#include <math.h>
#include <float.h>
#include <stdint.h>

#define T_SEQ 2048
#define NH 16
#define HD 128
#define DIM 2048
#define QKV_DIM 6144

// ---- mma.sync primitives (base ISA, works at compute_103) ----
__device__ __forceinline__ uint32_t smem_u32(const void* p) {
    uint32_t a;
    asm("{ .reg .u64 t; cvta.to.shared.u64 t, %1; cvt.u32.u64 %0, t; }"
        : "=r"(a) : "l"(p));
    return a;
}
__device__ __forceinline__ void ldsm4(uint32_t* r, uint32_t addr) {
    asm volatile("ldmatrix.sync.aligned.m8n8.x4.shared.b16 {%0,%1,%2,%3}, [%4];"
                 : "=r"(r[0]), "=r"(r[1]), "=r"(r[2]), "=r"(r[3]) : "r"(addr));
}
__device__ __forceinline__ void ldsm4t(uint32_t* r, uint32_t addr) {
    asm volatile("ldmatrix.sync.aligned.m8n8.x4.trans.shared.b16 {%0,%1,%2,%3}, [%4];"
                 : "=r"(r[0]), "=r"(r[1]), "=r"(r[2]), "=r"(r[3]) : "r"(addr));
}
__device__ __forceinline__ void mma_f16(float* c, const uint32_t* a, const uint32_t* b) {
    asm volatile(
        "mma.sync.aligned.m16n8k16.row.col.f32.f16.f16.f32 "
        "{%0,%1,%2,%3}, {%4,%5,%6,%7}, {%8,%9}, {%0,%1,%2,%3};"
        : "+f"(c[0]), "+f"(c[1]), "+f"(c[2]), "+f"(c[3])
        : "r"(a[0]), "r"(a[1]), "r"(a[2]), "r"(a[3]), "r"(b[0]), "r"(b[1]));
}
__device__ __forceinline__ void cp_async16(uint32_t saddr, const void* gptr) {
    asm volatile("cp.async.cg.shared.global [%0], [%1], 16;" :: "r"(saddr), "l"(gptr));
}
#define CP_COMMIT() asm volatile("cp.async.commit_group;" ::: "memory")
#define CP_WAIT(n)  asm volatile("cp.async.wait_group %0;" :: "n"(n) : "memory")

// pack two floats into an f16x2 register (lo, hi) via PTX cvt
__device__ __forceinline__ uint32_t cvt_f16x2(float lo, float hi) {
    uint32_t r;
    asm("cvt.rn.f16x2.f32 %0, %1, %2;" : "=r"(r) : "f"(hi), "f"(lo));
    return r;
}

// fp16 2-term split of a float pair -> (hi half2, lo half2)
__device__ __forceinline__ void f16_split2(float x, float y, __half2* h, __half2* l) {
    __half2 hh = __floats2half2_rn(x, y);
    float rx = x - __half2float(__low2half(hh));
    float ry = y - __half2float(__high2half(hh));
    *h = hh;
    *l = __floats2half2_rn(rx, ry);
}

// ---------------- global scratch (allocation-free rule) ----------------
__device__ float g_qkv[2L * T_SEQ * QKV_DIM];
__device__ __half g_xh[4096L * DIM],  g_xl[4096L * DIM];
__device__ __half g_wq1[(long)QKV_DIM * DIM];
__device__ __half g_wo1[(long)DIM * DIM];
__device__ __half g_ath[4096L * DIM], g_atl[4096L * DIM];
// fp16 q (2-term), k (single), v (2-term), head-contiguous
__device__ __half g_qh16[2L * NH * T_SEQ * HD], g_ql16[2L * NH * T_SEQ * HD];
__device__ __half g_k16[2L * NH * T_SEQ * HD];
__device__ __half g_vh16[2L * NH * T_SEQ * HD], g_vl16[2L * NH * T_SEQ * HD];

// ---------------------------------------------------------------------------
// fused pre-convert: x -> fp16 hi/lo, w_qkv/w_out -> single fp16
// ---------------------------------------------------------------------------
#define N4_X  (4096 * DIM / 4)
#define N4_WQ (QKV_DIM * DIM / 4)
#define N4_WO (DIM * DIM / 4)

__global__ __launch_bounds__(256) void split_all(const float* __restrict__ x,
                                                 const float* __restrict__ wq,
                                                 const float* __restrict__ wo) {
    int i = blockIdx.x * 256 + threadIdx.x;
    if (i < N4_X) {
        float4 v = ((const float4*)x)[i];
        __half2 h0, l0, h1, l1;
        f16_split2(v.x, v.y, &h0, &l0);
        f16_split2(v.z, v.w, &h1, &l1);
        ((__half2*)g_xh)[i * 2]     = h0;
        ((__half2*)g_xh)[i * 2 + 1] = h1;
        ((__half2*)g_xl)[i * 2]     = l0;
        ((__half2*)g_xl)[i * 2 + 1] = l1;
    } else if (i < N4_X + N4_WQ) {
        int j = i - N4_X;
        float4 v = ((const float4*)wq)[j];
        ((__half2*)g_wq1)[j * 2]     = __floats2half2_rn(v.x, v.y);
        ((__half2*)g_wq1)[j * 2 + 1] = __floats2half2_rn(v.z, v.w);
    } else if (i < N4_X + N4_WQ + N4_WO) {
        int j = i - N4_X - N4_WQ;
        float4 v = ((const float4*)wo)[j];
        ((__half2*)g_wo1)[j * 2]     = __floats2half2_rn(v.x, v.y);
        ((__half2*)g_wo1)[j * 2 + 1] = __floats2half2_rn(v.z, v.w);
    }
}

// ---------------------------------------------------------------------------
// fp16 2-term GEMM: C = (Ah+Al) * B1^T. (R15 passing version, unchanged)
// ---------------------------------------------------------------------------
#define NSTG 4
#define STG_SZ 18432
#define GEMM_SMEM (NSTG * STG_SZ)   // 73728 B

__global__ __launch_bounds__(128, 2) void gemm_f16_2t(
    const __half* __restrict__ Ah, const __half* __restrict__ Al,
    const __half* __restrict__ B1,
    float* __restrict__ C, int N, int K) {
    extern __shared__ char sm[];
    uint32_t sb = smem_u32(sm);
    int tid = threadIdx.x, lane = tid & 31, wid = tid >> 5;
    int wm = wid >> 1, wn = wid & 1;

    size_t arow = (size_t)blockIdx.y * 128;
    size_t brow = (size_t)blockIdx.x * 128;

    int cprow = tid >> 1;
    int half = tid & 1;
    uint32_t cpso0 = (uint32_t)(cprow * 48 + half * 16);
    uint32_t cpso1 = (uint32_t)((cprow + 64) * 48 + half * 16);
    const __half* pAh = Ah + (arow + cprow) * K + half * 8;
    const __half* pAl = Al + (arow + cprow) * K + half * 8;
    const __half* pB1 = B1 + (brow + cprow) * K + half * 8;
    size_t r64 = (size_t)64 * K;

    uint32_t a_off = (uint32_t)((wm * 64 + (lane & 15)) * 48 + ((lane >> 4) * 8) * 2);
    uint32_t b_off = (uint32_t)((wn * 64 + (lane >> 4) * 8 + (lane & 7)) * 48 +
                                (((lane >> 3) & 1) * 8) * 2);

    float acc[4][8][4];
#pragma unroll
    for (int i = 0; i < 4; i++)
#pragma unroll
        for (int j = 0; j < 8; j++)
#pragma unroll
            for (int q = 0; q < 4; q++) acc[i][j][q] = 0.f;

    const int NC = K / 16;

#define ISSUE(cidx)                                                            \
    do {                                                                       \
        uint32_t bufb = sb + (uint32_t)((cidx) & 3) * STG_SZ;                  \
        int koff = (cidx) * 16;                                                \
        cp_async16(bufb + cpso0,         pAh + koff);                          \
        cp_async16(bufb + cpso1,         pAh + r64 + koff);                    \
        cp_async16(bufb + 6144 + cpso0,  pAl + koff);                          \
        cp_async16(bufb + 6144 + cpso1,  pAl + r64 + koff);                    \
        cp_async16(bufb + 12288 + cpso0, pB1 + koff);                          \
        cp_async16(bufb + 12288 + cpso1, pB1 + r64 + koff);                    \
        CP_COMMIT();                                                           \
    } while (0)

    ISSUE(0);
    ISSUE(1);
    ISSUE(2);

    for (int c = 0; c < NC; ++c) {
        int rem = NC - 1 - c;
        if (rem >= 2)      { CP_WAIT(2); }
        else if (rem == 1) { CP_WAIT(1); }
        else               { CP_WAIT(0); }
        __syncthreads();
        if (c + 3 < NC) ISSUE(c + 3);

        uint32_t base = sb + (uint32_t)(c & 3) * STG_SZ;

        uint32_t BF[4][4];
#pragma unroll
        for (int p = 0; p < 4; p++)
            ldsm4(BF[p], base + 12288 + b_off + p * 768);

        uint32_t AHp[2][4], ALp[2][4];
        ldsm4(AHp[0], base + a_off);
        ldsm4(ALp[0], base + a_off + 6144);
#pragma unroll
        for (int mt = 0; mt < 4; mt++) {
            int cur = mt & 1, nxt = cur ^ 1;
            if (mt < 3) {
                uint32_t ad = base + a_off + (mt + 1) * 768;
                ldsm4(AHp[nxt], ad);
                ldsm4(ALp[nxt], ad + 6144);
            }
#pragma unroll
            for (int nt = 0; nt < 8; nt++)
                mma_f16(acc[mt][nt], AHp[cur], &BF[nt >> 1][(nt & 1) * 2]);
#pragma unroll
            for (int nt = 0; nt < 8; nt++)
                mma_f16(acc[mt][nt], ALp[cur], &BF[nt >> 1][(nt & 1) * 2]);
        }
    }

    int g = lane >> 2, tg = lane & 3;
#pragma unroll
    for (int mt = 0; mt < 4; mt++) {
        int row = blockIdx.y * 128 + wm * 64 + mt * 16 + g;
#pragma unroll
        for (int nt = 0; nt < 8; nt++) {
            int col = blockIdx.x * 128 + wn * 64 + nt * 8 + tg * 2;
            *(float2*)(C + (size_t)row * N + col) =
                make_float2(acc[mt][nt][0], acc[mt][nt][1]);
            *(float2*)(C + (size_t)(row + 8) * N + col) =
                make_float2(acc[mt][nt][2], acc[mt][nt][3]);
        }
    }
}

// ---------------------------------------------------------------------------
// RoPE + fp16 conversion: q -> 2-term, k -> single, v -> 2-term.
// ---------------------------------------------------------------------------
__global__ __launch_bounds__(256) void rope_convert() {
    int idx = blockIdx.x * 256 + threadIdx.x;
    int p = idx & 63;
    int h = (idx >> 6) & 15;
    int t = (idx >> 10) & 2047;
    int b = idx >> 21;

    float inv_freq = powf(10000.0f, -(float)p * (1.0f / 64.0f));
    float ang = (float)t * inv_freq;
    float s, c;
    sincosf(ang, &s, &c);

    size_t src = ((size_t)(b * T_SEQ + t)) * QKV_DIM + h * HD + p;
    size_t dst = ((size_t)((b * NH + h) * T_SEQ) + t) * HD + p;

    float q1 = g_qkv[src], q2 = g_qkv[src + 64];
    float qr1 = q1 * c - q2 * s, qr2 = q1 * s + q2 * c;
    __half hq1 = __float2half_rn(qr1);
    __half hq2 = __float2half_rn(qr2);
    g_qh16[dst]      = hq1;
    g_qh16[dst + 64] = hq2;
    g_ql16[dst]      = __float2half_rn(qr1 - __half2float(hq1));
    g_ql16[dst + 64] = __float2half_rn(qr2 - __half2float(hq2));

    float k1 = g_qkv[src + DIM], k2 = g_qkv[src + DIM + 64];
    g_k16[dst]      = __float2half_rn(k1 * c - k2 * s);
    g_k16[dst + 64] = __float2half_rn(k1 * s + k2 * c);

    float v1 = g_qkv[src + 2 * DIM], v2 = g_qkv[src + 2 * DIM + 64];
    __half hv1 = __float2half_rn(v1);
    __half hv2 = __float2half_rn(v2);
    g_vh16[dst]      = hv1;
    g_vh16[dst + 64] = hv2;
    g_vl16[dst]      = __float2half_rn(v1 - __half2float(hv1));
    g_vl16[dst + 64] = __float2half_rn(v2 - __half2float(hv2));
}

// ---------------------------------------------------------------------------
// fp16 tensor-core causal flash attention, BQ=64, 2 CTAs/SM.
// S = (Qh+Ql)K1^T (2-term), PV = P1(Vh+Vl) (2-term). 256 MMAs/tile (was 384).
// ---------------------------------------------------------------------------
#define SST 272
#define O_QH 0
#define O_QL 17408
#define O_K1 34816
#define O_VH 52224
#define O_VL 69632
#define ATTN_SMEM2 87040

__global__ __launch_bounds__(128, 2) void attn_mma() {
    extern __shared__ char sm[];
    uint32_t sb = smem_u32(sm);
    int tid = threadIdx.x, lane = tid & 31, w = tid >> 5;
    int qt = blockIdx.x, hd = blockIdx.y, b = blockIdx.z;
    int q0 = qt * 64;
    size_t hb = ((size_t)(b * NH + hd)) * T_SEQ;

    {
        const char* qh_g = (const char*)(g_qh16 + (hb + q0) * HD);
        const char* ql_g = (const char*)(g_ql16 + (hb + q0) * HD);
#pragma unroll
        for (int i = 0; i < 8; i++) {
            int idx = tid + i * 128;
            int r = idx >> 4, ch = idx & 15;
            int so = r * SST + ch * 16, go = r * 256 + ch * 16;
            *(uint4*)(sm + O_QH + so) = *(const uint4*)(qh_g + go);
            *(uint4*)(sm + O_QL + so) = *(const uint4*)(ql_g + go);
        }
    }
    __syncthreads();

    int g = lane >> 2, tg = lane & 3;
    uint32_t q_off = (uint32_t)((w * 16 + (lane & 15)) * SST + ((lane >> 4) * 8) * 2);
    uint32_t kb_off = (uint32_t)((((lane >> 4) * 8) + (lane & 7)) * SST +
                                 (((lane >> 3) & 1) * 8) * 2);
    uint32_t v_off = (uint32_t)((lane & 15) * SST + ((lane >> 4) * 8) * 2);

    uint32_t QH[8][4], QL[8][4];
#pragma unroll
    for (int ks = 0; ks < 8; ++ks) {
        ldsm4(QH[ks], sb + O_QH + q_off + ks * 32);
        ldsm4(QL[ks], sb + O_QL + q_off + ks * 32);
    }

    float o[16][4];
#pragma unroll
    for (int i = 0; i < 16; i++)
#pragma unroll
        for (int j = 0; j < 4; j++) o[i][j] = 0.f;

    float m0 = -1e30f, m1 = -1e30f, l0 = 0.f, l1 = 0.f;
    const float scale = 0.08838834764831845f;

    for (int kt = 0; kt <= qt; ++kt) {
        int k0 = kt * 64;
        __syncthreads();
        {
            const char* k_g  = (const char*)(g_k16 + (hb + k0) * HD);
            const char* vh_g = (const char*)(g_vh16 + (hb + k0) * HD);
            const char* vl_g = (const char*)(g_vl16 + (hb + k0) * HD);
#pragma unroll
            for (int i = 0; i < 8; i++) {
                int idx = tid + i * 128;
                int r = idx >> 4, ch = idx & 15;
                int so = r * SST + ch * 16, go = r * 256 + ch * 16;
                *(uint4*)(sm + O_K1 + so) = *(const uint4*)(k_g + go);
                *(uint4*)(sm + O_VH + so) = *(const uint4*)(vh_g + go);
                *(uint4*)(sm + O_VL + so) = *(const uint4*)(vl_g + go);
            }
        }
        __syncthreads();

        float st[8][4];
#pragma unroll
        for (int i = 0; i < 8; i++)
#pragma unroll
            for (int j = 0; j < 4; j++) st[i][j] = 0.f;

#pragma unroll
        for (int ks = 0; ks < 8; ++ks) {
#pragma unroll
            for (int p = 0; p < 4; ++p) {
                uint32_t K4[4];
                ldsm4(K4, sb + O_K1 + kb_off + p * 16 * SST + ks * 32);
                mma_f16(st[2 * p], QH[ks], K4);
                mma_f16(st[2 * p], QL[ks], K4);
                mma_f16(st[2 * p + 1], QH[ks], K4 + 2);
                mma_f16(st[2 * p + 1], QL[ks], K4 + 2);
            }
        }

        int rowg = q0 + w * 16 + g;
        bool diag = (kt == qt);
        float mx0 = -1e30f, mx1 = -1e30f;
#pragma unroll
        for (int nt = 0; nt < 8; ++nt) {
            int c0 = k0 + nt * 8 + 2 * tg;
            st[nt][0] *= scale; st[nt][1] *= scale;
            st[nt][2] *= scale; st[nt][3] *= scale;
            if (diag) {
                if (c0 > rowg)         st[nt][0] = -1e30f;
                if (c0 + 1 > rowg)     st[nt][1] = -1e30f;
                if (c0 > rowg + 8)     st[nt][2] = -1e30f;
                if (c0 + 1 > rowg + 8) st[nt][3] = -1e30f;
            }
            mx0 = fmaxf(mx0, fmaxf(st[nt][0], st[nt][1]));
            mx1 = fmaxf(mx1, fmaxf(st[nt][2], st[nt][3]));
        }
        mx0 = fmaxf(mx0, __shfl_xor_sync(0xffffffffu, mx0, 1));
        mx0 = fmaxf(mx0, __shfl_xor_sync(0xffffffffu, mx0, 2));
        mx1 = fmaxf(mx1, __shfl_xor_sync(0xffffffffu, mx1, 1));
        mx1 = fmaxf(mx1, __shfl_xor_sync(0xffffffffu, mx1, 2));

        float mn0 = fmaxf(m0, mx0), mn1 = fmaxf(m1, mx1);
        float al0 = __expf(m0 - mn0), al1 = __expf(m1 - mn1);
        float s0 = 0.f, s1 = 0.f;
#pragma unroll
        for (int nt = 0; nt < 8; ++nt) {
            st[nt][0] = __expf(st[nt][0] - mn0);
            st[nt][1] = __expf(st[nt][1] - mn0);
            st[nt][2] = __expf(st[nt][2] - mn1);
            st[nt][3] = __expf(st[nt][3] - mn1);
            s0 += st[nt][0] + st[nt][1];
            s1 += st[nt][2] + st[nt][3];
        }
        s0 += __shfl_xor_sync(0xffffffffu, s0, 1);
        s0 += __shfl_xor_sync(0xffffffffu, s0, 2);
        s1 += __shfl_xor_sync(0xffffffffu, s1, 1);
        s1 += __shfl_xor_sync(0xffffffffu, s1, 2);
        l0 = l0 * al0 + s0;
        l1 = l1 * al1 + s1;
        m0 = mn0; m1 = mn1;

#pragma unroll
        for (int i = 0; i < 16; i++) {
            o[i][0] *= al0; o[i][1] *= al0;
            o[i][2] *= al1; o[i][3] *= al1;
        }

#pragma unroll
        for (int ks = 0; ks < 4; ++ks) {
            uint32_t P1[4];
            P1[0] = cvt_f16x2(st[2 * ks][0], st[2 * ks][1]);
            P1[1] = cvt_f16x2(st[2 * ks][2], st[2 * ks][3]);
            P1[2] = cvt_f16x2(st[2 * ks + 1][0], st[2 * ks + 1][1]);
            P1[3] = cvt_f16x2(st[2 * ks + 1][2], st[2 * ks + 1][3]);
#pragma unroll
            for (int np = 0; np < 8; ++np) {
                uint32_t VH4[4], VL4[4];
                uint32_t vo = v_off + ks * 16 * SST + np * 32;
                ldsm4t(VH4, sb + O_VH + vo);
                ldsm4t(VL4, sb + O_VL + vo);
                mma_f16(o[2 * np], P1, VH4);
                mma_f16(o[2 * np], P1, VL4);
                mma_f16(o[2 * np + 1], P1, VH4 + 2);
                mma_f16(o[2 * np + 1], P1, VL4 + 2);
            }
        }
    }

    // finalize: write fp16 2-term split for the out-projection
    float inv0 = 1.f / l0, inv1 = 1.f / l1;
    int r0 = q0 + w * 16 + g;
    size_t base0 = ((size_t)(b * T_SEQ) + r0) * DIM + hd * HD;
    size_t base1 = base0 + (size_t)8 * DIM;
#pragma unroll
    for (int np = 0; np < 16; ++np) {
        int col = np * 8 + 2 * tg;
        float v0 = o[np][0] * inv0, v1 = o[np][1] * inv0;
        float v2 = o[np][2] * inv1, v3 = o[np][3] * inv1;
        __half2 h, l;
        f16_split2(v0, v1, &h, &l);
        *(__half2*)(g_ath + base0 + col) = h;
        *(__half2*)(g_atl + base0 + col) = l;
        f16_split2(v2, v3, &h, &l);
        *(__half2*)(g_ath + base1 + col) = h;
        *(__half2*)(g_atl + base1 + col) = l;
    }
}

// ---------------------------------------------------------------------------
extern "C" void kernel_launch(void* const* d_in, const int* in_sizes, int n_in,
                              void* d_out, int out_size) {
    const float* x     = (const float*)d_in[0];
    const float* w_qkv = (const float*)d_in[1];
    const float* w_out = (const float*)d_in[2];
    float* out = (float*)d_out;

    float* qkv_ptr; cudaGetSymbolAddress((void**)&qkv_ptr, g_qkv);
    __half *xh, *xl, *wq1, *wo1, *ath, *atl;
    cudaGetSymbolAddress((void**)&xh, g_xh);   cudaGetSymbolAddress((void**)&xl, g_xl);
    cudaGetSymbolAddress((void**)&wq1, g_wq1); cudaGetSymbolAddress((void**)&wo1, g_wo1);
    cudaGetSymbolAddress((void**)&ath, g_ath); cudaGetSymbolAddress((void**)&atl, g_atl);

    cudaFuncSetAttribute(gemm_f16_2t, cudaFuncAttributeMaxDynamicSharedMemorySize, GEMM_SMEM);
    cudaFuncSetAttribute(attn_mma, cudaFuncAttributeMaxDynamicSharedMemorySize, ATTN_SMEM2);

    // 0) fused pre-convert
    int total4 = N4_X + N4_WQ + N4_WO;
    split_all<<<(total4 + 255) / 256, 256>>>(x, w_qkv, w_out);

    // 1) QKV projection (fp16 2-term)
    gemm_f16_2t<<<dim3(QKV_DIM / 128, 4096 / 128), 128, GEMM_SMEM>>>(
        xh, xl, wq1, qkv_ptr, QKV_DIM, DIM);
    // 2) RoPE + fp16 conversion
    rope_convert<<<(2 * T_SEQ * NH * 64) / 256, 256>>>();
    // 3) causal attention (fp16 2-term, BQ=64, 2 CTAs/SM)
    attn_mma<<<dim3(T_SEQ / 64, NH, 2), 128, ATTN_SMEM2>>>();
    // 4) output projection (fp16 2-term)
    gemm_f16_2t<<<dim3(DIM / 128, 4096 / 128), 128, GEMM_SMEM>>>(
        ath, atl, wo1, out, DIM, DIM);
}